// round 13
// baseline (speedup 1.0000x reference)
#include <cuda_runtime.h>
#include <cuda_fp16.h>
#include <cstdint>

// Problem sizes
static constexpr int NTOK = 8192;
static constexpr int DM   = 1024;
static constexpr int NEXP = 8;
static constexpr int RLO  = 16;
static constexpr int KC   = 1152;   // 1024 + 128 lora-combine columns

// Scratch (device globals; no runtime allocation allowed)
__device__ __half g_xh[(long)NTOK * KC];    // [ x | c ]        (rows: token)
__device__ __half g_wh[(long)DM * KC];      // [ W_base | B^T ] (rows: out dim)
__device__ __half g_ah[128L * DM];          // ah[j][k] = A[e][k][r], j=e*16+r
__device__ float4 g_gate[NTOK];             // {w0, w1, bits(e0), bits(e1)}

// ---------------------------------------------------------------------------
// Helpers
// ---------------------------------------------------------------------------
static __device__ __forceinline__ uint32_t smem_u32(const void* p) {
    uint32_t a;
    asm("{ .reg .u64 t; cvta.to.shared.u64 t, %1; cvt.u32.u64 %0, t; }" : "=r"(a) : "l"(p));
    return a;
}

#define CP_ASYNC16(saddr, gptr) \
    asm volatile("cp.async.cg.shared.global [%0], [%1], 16;" :: "r"(saddr), "l"(gptr))
#define CP_COMMIT() asm volatile("cp.async.commit_group;" ::: "memory")
#define CP_WAIT1()  asm volatile("cp.async.wait_group 1;" ::: "memory")

// m16n8k16 fp16 MMA, fp32 accumulate
#define MMA_F16(d, a, b) \
    asm volatile("mma.sync.aligned.m16n8k16.row.col.f32.f16.f16.f32 " \
        "{%0,%1,%2,%3}, {%4,%5,%6,%7}, {%8,%9}, {%0,%1,%2,%3};" \
        : "+f"((d)[0]), "+f"((d)[1]), "+f"((d)[2]), "+f"((d)[3]) \
        : "r"((a)[0]), "r"((a)[1]), "r"((a)[2]), "r"((a)[3]), \
          "r"((b)[0]), "r"((b)[1]))

#define LDMX4(r0, r1, r2, r3, addr) \
    asm volatile("ldmatrix.sync.aligned.m8n8.x4.shared.b16 {%0,%1,%2,%3}, [%4];" \
        : "=r"(r0), "=r"(r1), "=r"(r2), "=r"(r3) : "r"(addr))

// ---------------------------------------------------------------------------
// Fused prep + gate-logit kernel (single launch).
// Segments (all boundaries 256-thread-block aligned):
//   [x MLP4: 524288][W MLP4: 65536][B: 131072][A: 131072][logits: 131072]
// Logit segment: 2 tokens per warp, float4 loads, warp-shuffle reduce.
// ---------------------------------------------------------------------------
static constexpr long NX16 = (long)NTOK * DM / 16;  // 524288
static constexpr long NW16 = (long)DM * DM / 16;    // 65536
static constexpr long NB   = 128L * DM;             // 131072
static constexpr long NA   = 128L * DM;             // 131072
static constexpr long NL   = (long)(NTOK / 2) * 32; // 131072 (warp per 2 tokens)
static constexpr long NPREP = NX16 + NW16 + NB + NA + NL;

__global__ void prep_logit_kernel(const float* __restrict__ x,
                                  const float* __restrict__ Wb,
                                  const float* __restrict__ B,
                                  const float* __restrict__ A,
                                  const float* __restrict__ Wg) {
    long i = (long)blockIdx.x * blockDim.x + threadIdx.x;
    if (i < NX16) {
        long base4 = (i >> 8) * 1024 + (i & 255);
#pragma unroll
        for (int q = 0; q < 4; q++) {
            long i4 = base4 + q * 256;
            long n = i4 >> 8, d = (i4 & 255) * 4;
            float4 v = *(const float4*)(x + i4 * 4);
            __half2* dst = (__half2*)(g_xh + n * KC + d);
            dst[0] = __floats2half2_rn(v.x, v.y);
            dst[1] = __floats2half2_rn(v.z, v.w);
        }
        return;
    }
    i -= NX16;
    if (i < NW16) {
        long base4 = (i >> 8) * 1024 + (i & 255);
#pragma unroll
        for (int q = 0; q < 4; q++) {
            long i4 = base4 + q * 256;
            long n = i4 >> 8, k = (i4 & 255) * 4;
            float4 v = *(const float4*)(Wb + i4 * 4);
            __half2* dst = (__half2*)(g_wh + n * KC + k);
            dst[0] = __floats2half2_rn(v.x, v.y);
            dst[1] = __floats2half2_rn(v.z, v.w);
        }
        return;
    }
    i -= NW16;
    if (i < NB) {   // B[e][r][d] -> g_wh[d][1024 + j], j = e*16+r = i>>10
        int j = (int)(i >> 10), d = (int)(i & 1023);
        g_wh[(long)d * KC + 1024 + j] = __float2half_rn(B[i]);
        return;
    }
    i -= NB;
    if (i < NA) {   // A[e][d][r] -> g_ah[j][k] = A[e][k][r]
        int j = (int)(i >> 10), k = (int)(i & 1023);
        int e = j >> 4, r = j & 15;
        g_ah[(long)j * DM + k] = __float2half_rn(A[((long)e * DM + k) * RLO + r]);
        return;
    }
    i -= NA;
    if (i < NL) {   // fp32 gate logits + top-2 softmax, 2 tokens per warp
        int warp = (int)(i >> 5);               // 0..4095
        int lane = threadIdx.x & 31;
        long t0 = (long)warp * 2;
        const float4* x4 = (const float4*)x;
        const float4* w4 = (const float4*)Wg;

        float acc[NEXP][2];
#pragma unroll
        for (int e = 0; e < NEXP; e++) { acc[e][0] = 0.f; acc[e][1] = 0.f; }

#pragma unroll
        for (int it = 0; it < 8; it++) {
            int c4 = it * 32 + lane;            // float4 column 0..255
            float4 xa = x4[t0 * 256 + c4];
            float4 xb = x4[(t0 + 1) * 256 + c4];
#pragma unroll
            for (int e = 0; e < NEXP; e++) {
                float4 wv = w4[e * 256 + c4];
                acc[e][0] = fmaf(xa.x, wv.x, fmaf(xa.y, wv.y,
                             fmaf(xa.z, wv.z, fmaf(xa.w, wv.w, acc[e][0]))));
                acc[e][1] = fmaf(xb.x, wv.x, fmaf(xb.y, wv.y,
                             fmaf(xb.z, wv.z, fmaf(xb.w, wv.w, acc[e][1]))));
            }
        }
#pragma unroll
        for (int e = 0; e < NEXP; e++)
#pragma unroll
            for (int t = 0; t < 2; t++)
#pragma unroll
                for (int s = 16; s > 0; s >>= 1)
                    acc[e][t] += __shfl_xor_sync(0xFFFFFFFFu, acc[e][t], s);

        if (lane < 2) {
            float v0 = -1e30f; int e0 = 0;
#pragma unroll
            for (int e = 0; e < NEXP; e++)
                if (acc[e][lane] > v0) { v0 = acc[e][lane]; e0 = e; }
            float v1 = -1e30f; int e1 = 0;
#pragma unroll
            for (int e = 0; e < NEXP; e++)
                if (e != e0 && acc[e][lane] > v1) { v1 = acc[e][lane]; e1 = e; }
            float b  = expf(v1 - v0);
            float w0 = 1.f / (1.f + b);
            float w1 = b * w0;
            g_gate[t0 + lane] = make_float4(w0, w1, __int_as_float(e0), __int_as_float(e1));
        }
    }
}

static constexpr int LDH = 72;                          // row pad: 64+8 halves
static constexpr int NSTAGE = 2;

// ---------------------------------------------------------------------------
// GEMM0 + gate epilogue: h[64x128] = x @ A^T (fp16 MMA, fp32 accum); epilogue
// scales h by precomputed gate weights and writes fp16 c into g_xh tail.
// BM=64, BN=128, 8 warps (2 x 4), warp tile 32x32, 2-stage, OCC=3.
// ---------------------------------------------------------------------------
__global__ void __launch_bounds__(256, 3)
gemm0_gate(const __half* __restrict__ Am, const __half* __restrict__ Bm) {
    constexpr int BM = 64, BN = 128, MI = 2, NJ = 4;
    constexpr int KT = DM / 64;                         // 16
    constexpr int STAGE_BYTES = (BM + BN) * LDH * 2;    // 27648

    extern __shared__ __align__(16) __half smem[];

    const int tid  = threadIdx.x;
    const int wid  = tid >> 5;
    const int lane = tid & 31;
    const int wm   = wid >> 2;        // 0..1
    const int wn   = wid & 3;         // 0..3
    const int g    = lane >> 2;
    const int t4   = lane & 3;
    const int m0   = blockIdx.x * BM;

    const uint32_t sbase = smem_u32(smem);
    const __half* Ab = Am + (long)m0 * KC;

    auto load_stage = [&](int kt, int stg) {
        const uint32_t sa = sbase + (uint32_t)stg * STAGE_BYTES;
        const uint32_t sb = sa + BM * LDH * 2;
        const __half* Asrc = Ab + (long)kt * 64;
        const __half* Bsrc = Bm + (long)kt * 64;
#pragma unroll
        for (int c = 0; c < BM * 8 / 256; c++) {        // 2
            int idx = c * 256 + tid;
            int row = idx >> 3, q = idx & 7;
            CP_ASYNC16(sa + (uint32_t)(row * LDH + q * 8) * 2,
                       Asrc + (long)row * KC + q * 8);
        }
#pragma unroll
        for (int c = 0; c < BN * 8 / 256; c++) {        // 4
            int idx = c * 256 + tid;
            int row = idx >> 3, q = idx & 7;
            CP_ASYNC16(sb + (uint32_t)(row * LDH + q * 8) * 2,
                       Bsrc + (long)row * DM + q * 8);
        }
        CP_COMMIT();
    };

    const int lrow = lane & 15;
    const int lcol = (lane >> 4) * 8;
    const uint32_t aoffh = (uint32_t)((wm * 32 + lrow) * LDH + lcol);
    const uint32_t boffh = (uint32_t)(BM * LDH + (wn * 32 + lrow) * LDH + lcol);

    float acc[MI][NJ][4];
#pragma unroll
    for (int i = 0; i < MI; i++)
#pragma unroll
        for (int j = 0; j < NJ; j++)
#pragma unroll
            for (int r = 0; r < 4; r++) acc[i][j][r] = 0.f;

    load_stage(0, 0);

    for (int kt = 0; kt < KT; kt++) {
        if (kt + 1 < KT) load_stage(kt + 1, (kt + 1) & 1);
        else CP_COMMIT();
        CP_WAIT1();
        __syncthreads();

        const uint32_t sa = sbase + (uint32_t)(kt & 1) * STAGE_BYTES;
#pragma unroll
        for (int ks = 0; ks < 4; ks++) {
            const uint32_t ksh = (uint32_t)(ks * 16) * 2;
            uint32_t a[MI][4];
#pragma unroll
            for (int i = 0; i < MI; i++)
                LDMX4(a[i][0], a[i][1], a[i][2], a[i][3],
                      sa + (aoffh + (uint32_t)(i * 16) * LDH) * 2 + ksh);
            uint32_t b[NJ][2];
#pragma unroll
            for (int jp = 0; jp < NJ / 2; jp++)
                LDMX4(b[jp * 2][0], b[jp * 2 + 1][0], b[jp * 2][1], b[jp * 2 + 1][1],
                      sa + (boffh + (uint32_t)(jp * 16) * LDH) * 2 + ksh);
#pragma unroll
            for (int i = 0; i < MI; i++)
#pragma unroll
                for (int j = 0; j < NJ; j++)
                    MMA_F16(acc[i][j], a[i], b[j]);
        }
        __syncthreads();
    }

    // Gate epilogue: c[token][col] = w(token, col>>4) * h ; write fp16 pairs.
#pragma unroll
    for (int i = 0; i < MI; i++) {
        int t0 = m0 + wm * 32 + i * 16 + g;
        int t1 = t0 + 8;
        float4 r0 = g_gate[t0];
        float4 r1 = g_gate[t1];
        int e0a = __float_as_int(r0.z), e1a = __float_as_int(r0.w);
        int e0b = __float_as_int(r1.z), e1b = __float_as_int(r1.w);
#pragma unroll
        for (int j = 0; j < NJ; j++) {
            int col = wn * 32 + j * 8 + 2 * t4;
            int e = col >> 4;                  // col, col+1 share the expert
            float wa = (e == e0a) ? r0.x : ((e == e1a) ? r0.y : 0.f);
            float wb = (e == e0b) ? r1.x : ((e == e1b) ? r1.y : 0.f);
            *(__half2*)(g_xh + (long)t0 * KC + 1024 + col) =
                __floats2half2_rn(wa * acc[i][j][0], wa * acc[i][j][1]);
            *(__half2*)(g_xh + (long)t1 * KC + 1024 + col) =
                __floats2half2_rn(wb * acc[i][j][2], wb * acc[i][j][3]);
        }
    }
}

// ---------------------------------------------------------------------------
// Output GEMM (round-10 proven): C = [x|c] @ [W|Bt]^T + bias.
// BM=128, BN=64, 8 warps (4 x 2), warp tile 32x32, 2-stage, OCC=4.
// ---------------------------------------------------------------------------
__global__ void __launch_bounds__(256, 4)
gemm1(const __half* __restrict__ A, const __half* __restrict__ Bm,
      float* __restrict__ C, const float* __restrict__ bias) {
    constexpr int BM = 128, BN = 64, MI = 2, NJ = 4;
    constexpr int KT = KC / 64;                         // 18
    constexpr int STAGE_BYTES = (BM + BN) * LDH * 2;    // 27648

    extern __shared__ __align__(16) __half smem[];

    const int tid  = threadIdx.x;
    const int wid  = tid >> 5;
    const int lane = tid & 31;
    const int wm   = wid >> 1;        // 0..3
    const int wn   = wid & 1;         // 0..1
    const int g    = lane >> 2;
    const int t4   = lane & 3;
    const int m0   = blockIdx.x * BM;
    const int n0   = blockIdx.y * BN;

    const uint32_t sbase = smem_u32(smem);
    const __half* Ab = A + (long)m0 * KC;
    const __half* Bb = Bm + (long)n0 * KC;

    auto load_stage = [&](int kt, int stg) {
        const uint32_t sa = sbase + (uint32_t)stg * STAGE_BYTES;
        const uint32_t sb = sa + BM * LDH * 2;
        const __half* Asrc = Ab + (long)kt * 64;
        const __half* Bsrc = Bb + (long)kt * 64;
#pragma unroll
        for (int c = 0; c < BM * 8 / 256; c++) {
            int idx = c * 256 + tid;
            int row = idx >> 3, q = idx & 7;
            CP_ASYNC16(sa + (uint32_t)(row * LDH + q * 8) * 2,
                       Asrc + (long)row * KC + q * 8);
        }
#pragma unroll
        for (int c = 0; c < BN * 8 / 256; c++) {
            int idx = c * 256 + tid;
            int row = idx >> 3, q = idx & 7;
            CP_ASYNC16(sb + (uint32_t)(row * LDH + q * 8) * 2,
                       Bsrc + (long)row * KC + q * 8);
        }
        CP_COMMIT();
    };

    const int lrow = lane & 15;
    const int lcol = (lane >> 4) * 8;
    const uint32_t aoffh = (uint32_t)((wm * 32 + lrow) * LDH + lcol);
    const uint32_t boffh = (uint32_t)(BM * LDH + (wn * 32 + lrow) * LDH + lcol);

    float acc[MI][NJ][4];
#pragma unroll
    for (int i = 0; i < MI; i++)
#pragma unroll
        for (int j = 0; j < NJ; j++)
#pragma unroll
            for (int r = 0; r < 4; r++) acc[i][j][r] = 0.f;

    load_stage(0, 0);

    for (int kt = 0; kt < KT; kt++) {
        if (kt + 1 < KT) load_stage(kt + 1, (kt + 1) & 1);
        else CP_COMMIT();
        CP_WAIT1();
        __syncthreads();

        const uint32_t sa = sbase + (uint32_t)(kt & 1) * STAGE_BYTES;
#pragma unroll
        for (int ks = 0; ks < 4; ks++) {
            const uint32_t ksh = (uint32_t)(ks * 16) * 2;
            uint32_t a[MI][4];
#pragma unroll
            for (int i = 0; i < MI; i++)
                LDMX4(a[i][0], a[i][1], a[i][2], a[i][3],
                      sa + (aoffh + (uint32_t)(i * 16) * LDH) * 2 + ksh);
            uint32_t b[NJ][2];
#pragma unroll
            for (int jp = 0; jp < NJ / 2; jp++)
                LDMX4(b[jp * 2][0], b[jp * 2 + 1][0], b[jp * 2][1], b[jp * 2 + 1][1],
                      sa + (boffh + (uint32_t)(jp * 16) * LDH) * 2 + ksh);
#pragma unroll
            for (int i = 0; i < MI; i++)
#pragma unroll
                for (int j = 0; j < NJ; j++)
                    MMA_F16(acc[i][j], a[i], b[j]);
        }
        __syncthreads();
    }

    // Epilogue
#pragma unroll
    for (int i = 0; i < MI; i++) {
        int row0 = m0 + wm * 32 + i * 16 + g;
#pragma unroll
        for (int j = 0; j < NJ; j++) {
            int col = n0 + wn * 32 + j * 8 + 2 * t4;
            float bx = bias[col], by = bias[col + 1];
            float2 v0 = { acc[i][j][0] + bx, acc[i][j][1] + by };
            float2 v1 = { acc[i][j][2] + bx, acc[i][j][3] + by };
            *(float2*)(C + (long)row0 * DM + col)       = v0;
            *(float2*)(C + (long)(row0 + 8) * DM + col) = v1;
        }
    }
}

static constexpr int SMEM_B0 = NSTAGE * (64 + 128) * LDH * 2;  // 55296
static constexpr int SMEM_B1 = NSTAGE * (128 + 64) * LDH * 2;  // 55296

// ---------------------------------------------------------------------------
// Launch
// ---------------------------------------------------------------------------
extern "C" void kernel_launch(void* const* d_in, const int* in_sizes, int n_in,
                              void* d_out, int out_size) {
    const float* x    = (const float*)d_in[0];
    const float* Wg   = (const float*)d_in[1];
    const float* A    = (const float*)d_in[2];
    const float* B    = (const float*)d_in[3];
    const float* Wb   = (const float*)d_in[4];
    const float* bias = (const float*)d_in[5];
    float* out = (float*)d_out;

    static bool attr_done = false;
    if (!attr_done) {
        cudaFuncSetAttribute(gemm0_gate, cudaFuncAttributeMaxDynamicSharedMemorySize, SMEM_B0);
        cudaFuncSetAttribute(gemm1, cudaFuncAttributeMaxDynamicSharedMemorySize, SMEM_B1);
        attr_done = true;
    }

    __half *xh, *wh, *ah;
    cudaGetSymbolAddress((void**)&xh, g_xh);
    cudaGetSymbolAddress((void**)&wh, g_wh);
    cudaGetSymbolAddress((void**)&ah, g_ah);

    // 1) fp16 operand staging + fp32 gate logits/top-2 (one launch, overlapped)
    prep_logit_kernel<<<(int)(NPREP / 256), 256>>>(x, Wb, B, A, Wg);

    // 2) h-GEMM with fused gate epilogue -> writes c-tail of g_xh directly
    gemm0_gate<<<NTOK / 64, 256, SMEM_B0>>>(xh, ah);

    // 3) fused output GEMM: out = [x|c] @ [W|Bt]^T + bias  (8192 x 1024 x 1152)
    gemm1<<<dim3(NTOK / 128, DM / 64), 256, SMEM_B1>>>(xh, wh, out, bias);
}

// round 14
// speedup vs baseline: 1.5287x; 1.5287x over previous
#include <cuda_runtime.h>
#include <cuda_fp16.h>
#include <cstdint>

// Problem sizes
static constexpr int NTOK = 8192;
static constexpr int DM   = 1024;
static constexpr int NEXP = 8;
static constexpr int RLO  = 16;
static constexpr int KC   = 1152;   // 1024 + 128 lora-combine columns

// Scratch (device globals; no runtime allocation allowed)
__device__ __half g_xh[(long)NTOK * KC];    // [ x | c ]        (rows: token)
__device__ __half g_wh[(long)DM * KC];      // [ W_base | B^T ] (rows: out dim)
__device__ __half g_ah[128L * DM];          // ah[j][k] = A[e][k][r], j=e*16+r
__device__ float4 g_gate[NTOK];             // {w0, w1, bits(e0), bits(e1)}

// ---------------------------------------------------------------------------
// Helpers
// ---------------------------------------------------------------------------
static __device__ __forceinline__ uint32_t smem_u32(const void* p) {
    uint32_t a;
    asm("{ .reg .u64 t; cvta.to.shared.u64 t, %1; cvt.u32.u64 %0, t; }" : "=r"(a) : "l"(p));
    return a;
}

#define CP_ASYNC16(saddr, gptr) \
    asm volatile("cp.async.cg.shared.global [%0], [%1], 16;" :: "r"(saddr), "l"(gptr))
#define CP_COMMIT() asm volatile("cp.async.commit_group;" ::: "memory")
#define CP_WAIT1()  asm volatile("cp.async.wait_group 1;" ::: "memory")

// m16n8k16 fp16 MMA, fp32 accumulate
#define MMA_F16(d, a, b) \
    asm volatile("mma.sync.aligned.m16n8k16.row.col.f32.f16.f16.f32 " \
        "{%0,%1,%2,%3}, {%4,%5,%6,%7}, {%8,%9}, {%0,%1,%2,%3};" \
        : "+f"((d)[0]), "+f"((d)[1]), "+f"((d)[2]), "+f"((d)[3]) \
        : "r"((a)[0]), "r"((a)[1]), "r"((a)[2]), "r"((a)[3]), \
          "r"((b)[0]), "r"((b)[1]))

#define LDMX4(r0, r1, r2, r3, addr) \
    asm volatile("ldmatrix.sync.aligned.m8n8.x4.shared.b16 {%0,%1,%2,%3}, [%4];" \
        : "=r"(r0), "=r"(r1), "=r"(r2), "=r"(r3) : "r"(addr))

// ---------------------------------------------------------------------------
// Fused prep + gate-logit kernel (single launch).
// Segments (all boundaries 256-thread-block aligned):
//   [x MLP4: 524288][W MLP4: 65536][B: 131072][A: 131072][logits: 262144]
// Logit segment: warp per token, float4 loads, low-register.
// __launch_bounds__(256, 5) caps regs (round-13 lesson: reg bill is global).
// ---------------------------------------------------------------------------
static constexpr long NX16 = (long)NTOK * DM / 16;  // 524288
static constexpr long NW16 = (long)DM * DM / 16;    // 65536
static constexpr long NB   = 128L * DM;             // 131072
static constexpr long NA   = 128L * DM;             // 131072
static constexpr long NL   = (long)NTOK * 32;       // 262144 (warp per token)
static constexpr long NPREP = NX16 + NW16 + NB + NA + NL;

__global__ void __launch_bounds__(256, 5)
prep_logit_kernel(const float* __restrict__ x,
                  const float* __restrict__ Wb,
                  const float* __restrict__ B,
                  const float* __restrict__ A,
                  const float* __restrict__ Wg) {
    long i = (long)blockIdx.x * blockDim.x + threadIdx.x;
    if (i < NX16) {
        long base4 = (i >> 8) * 1024 + (i & 255);
#pragma unroll
        for (int q = 0; q < 4; q++) {
            long i4 = base4 + q * 256;
            long n = i4 >> 8, d = (i4 & 255) * 4;
            float4 v = *(const float4*)(x + i4 * 4);
            __half2* dst = (__half2*)(g_xh + n * KC + d);
            dst[0] = __floats2half2_rn(v.x, v.y);
            dst[1] = __floats2half2_rn(v.z, v.w);
        }
        return;
    }
    i -= NX16;
    if (i < NW16) {
        long base4 = (i >> 8) * 1024 + (i & 255);
#pragma unroll
        for (int q = 0; q < 4; q++) {
            long i4 = base4 + q * 256;
            long n = i4 >> 8, k = (i4 & 255) * 4;
            float4 v = *(const float4*)(Wb + i4 * 4);
            __half2* dst = (__half2*)(g_wh + n * KC + k);
            dst[0] = __floats2half2_rn(v.x, v.y);
            dst[1] = __floats2half2_rn(v.z, v.w);
        }
        return;
    }
    i -= NW16;
    if (i < NB) {   // B[e][r][d] -> g_wh[d][1024 + j], j = e*16+r = i>>10
        int j = (int)(i >> 10), d = (int)(i & 1023);
        g_wh[(long)d * KC + 1024 + j] = __float2half_rn(B[i]);
        return;
    }
    i -= NB;
    if (i < NA) {   // A[e][d][r] -> g_ah[j][k] = A[e][k][r]
        int j = (int)(i >> 10), k = (int)(i & 1023);
        int e = j >> 4, r = j & 15;
        g_ah[(long)j * DM + k] = __float2half_rn(A[((long)e * DM + k) * RLO + r]);
        return;
    }
    i -= NA;
    if (i < NL) {   // fp32 gate logits + top-2 softmax, warp per token
        int warp = (int)(i >> 5);
        int lane = threadIdx.x & 31;
        const float4* x4 = (const float4*)(x + (long)warp * DM);
        const float4* w4 = (const float4*)Wg;

        float acc[NEXP];
#pragma unroll
        for (int e = 0; e < NEXP; e++) acc[e] = 0.f;

#pragma unroll
        for (int it = 0; it < 8; it++) {
            int c4 = it * 32 + lane;            // float4 column 0..255
            float4 xa = x4[c4];
#pragma unroll
            for (int e = 0; e < NEXP; e++) {
                float4 wv = w4[e * 256 + c4];
                acc[e] = fmaf(xa.x, wv.x, fmaf(xa.y, wv.y,
                          fmaf(xa.z, wv.z, fmaf(xa.w, wv.w, acc[e]))));
            }
        }
#pragma unroll
        for (int e = 0; e < NEXP; e++)
#pragma unroll
            for (int s = 16; s > 0; s >>= 1)
                acc[e] += __shfl_xor_sync(0xFFFFFFFFu, acc[e], s);

        if (lane == 0) {
            float v0 = -1e30f; int e0 = 0;
#pragma unroll
            for (int e = 0; e < NEXP; e++) if (acc[e] > v0) { v0 = acc[e]; e0 = e; }
            float v1 = -1e30f; int e1 = 0;
#pragma unroll
            for (int e = 0; e < NEXP; e++)
                if (e != e0 && acc[e] > v1) { v1 = acc[e]; e1 = e; }
            float b  = expf(v1 - v0);
            float w0 = 1.f / (1.f + b);
            float w1 = b * w0;
            g_gate[warp] = make_float4(w0, w1, __int_as_float(e0), __int_as_float(e1));
        }
    }
}

static constexpr int LDH = 72;                          // row pad: 64+8 halves
static constexpr int NSTAGE = 2;

// ---------------------------------------------------------------------------
// GEMM0 + gate epilogue: h[64x128] = x @ A^T (fp16 MMA, fp32 accum); epilogue
// scales h by precomputed gate weights and writes fp16 c into g_xh tail.
// BM=64, BN=128, 8 warps (2 x 4), warp tile 32x32, 2-stage, OCC=3.
// ---------------------------------------------------------------------------
__global__ void __launch_bounds__(256, 3)
gemm0_gate(const __half* __restrict__ Am, const __half* __restrict__ Bm) {
    constexpr int BM = 64, BN = 128, MI = 2, NJ = 4;
    constexpr int KT = DM / 64;                         // 16
    constexpr int STAGE_BYTES = (BM + BN) * LDH * 2;    // 27648

    extern __shared__ __align__(16) __half smem[];

    const int tid  = threadIdx.x;
    const int wid  = tid >> 5;
    const int lane = tid & 31;
    const int wm   = wid >> 2;        // 0..1
    const int wn   = wid & 3;         // 0..3
    const int g    = lane >> 2;
    const int t4   = lane & 3;
    const int m0   = blockIdx.x * BM;

    const uint32_t sbase = smem_u32(smem);
    const __half* Ab = Am + (long)m0 * KC;

    auto load_stage = [&](int kt, int stg) {
        const uint32_t sa = sbase + (uint32_t)stg * STAGE_BYTES;
        const uint32_t sb = sa + BM * LDH * 2;
        const __half* Asrc = Ab + (long)kt * 64;
        const __half* Bsrc = Bm + (long)kt * 64;
#pragma unroll
        for (int c = 0; c < BM * 8 / 256; c++) {        // 2
            int idx = c * 256 + tid;
            int row = idx >> 3, q = idx & 7;
            CP_ASYNC16(sa + (uint32_t)(row * LDH + q * 8) * 2,
                       Asrc + (long)row * KC + q * 8);
        }
#pragma unroll
        for (int c = 0; c < BN * 8 / 256; c++) {        // 4
            int idx = c * 256 + tid;
            int row = idx >> 3, q = idx & 7;
            CP_ASYNC16(sb + (uint32_t)(row * LDH + q * 8) * 2,
                       Bsrc + (long)row * DM + q * 8);
        }
        CP_COMMIT();
    };

    const int lrow = lane & 15;
    const int lcol = (lane >> 4) * 8;
    const uint32_t aoffh = (uint32_t)((wm * 32 + lrow) * LDH + lcol);
    const uint32_t boffh = (uint32_t)(BM * LDH + (wn * 32 + lrow) * LDH + lcol);

    float acc[MI][NJ][4];
#pragma unroll
    for (int i = 0; i < MI; i++)
#pragma unroll
        for (int j = 0; j < NJ; j++)
#pragma unroll
            for (int r = 0; r < 4; r++) acc[i][j][r] = 0.f;

    load_stage(0, 0);

    for (int kt = 0; kt < KT; kt++) {
        if (kt + 1 < KT) load_stage(kt + 1, (kt + 1) & 1);
        else CP_COMMIT();
        CP_WAIT1();
        __syncthreads();

        const uint32_t sa = sbase + (uint32_t)(kt & 1) * STAGE_BYTES;
#pragma unroll
        for (int ks = 0; ks < 4; ks++) {
            const uint32_t ksh = (uint32_t)(ks * 16) * 2;
            uint32_t a[MI][4];
#pragma unroll
            for (int i = 0; i < MI; i++)
                LDMX4(a[i][0], a[i][1], a[i][2], a[i][3],
                      sa + (aoffh + (uint32_t)(i * 16) * LDH) * 2 + ksh);
            uint32_t b[NJ][2];
#pragma unroll
            for (int jp = 0; jp < NJ / 2; jp++)
                LDMX4(b[jp * 2][0], b[jp * 2 + 1][0], b[jp * 2][1], b[jp * 2 + 1][1],
                      sa + (boffh + (uint32_t)(jp * 16) * LDH) * 2 + ksh);
#pragma unroll
            for (int i = 0; i < MI; i++)
#pragma unroll
                for (int j = 0; j < NJ; j++)
                    MMA_F16(acc[i][j], a[i], b[j]);
        }
        __syncthreads();
    }

    // Gate epilogue: c[token][col] = w(token, col>>4) * h ; write fp16 pairs.
#pragma unroll
    for (int i = 0; i < MI; i++) {
        int t0 = m0 + wm * 32 + i * 16 + g;
        int t1 = t0 + 8;
        float4 r0 = g_gate[t0];
        float4 r1 = g_gate[t1];
        int e0a = __float_as_int(r0.z), e1a = __float_as_int(r0.w);
        int e0b = __float_as_int(r1.z), e1b = __float_as_int(r1.w);
#pragma unroll
        for (int j = 0; j < NJ; j++) {
            int col = wn * 32 + j * 8 + 2 * t4;
            int e = col >> 4;                  // col, col+1 share the expert
            float wa = (e == e0a) ? r0.x : ((e == e1a) ? r0.y : 0.f);
            float wb = (e == e0b) ? r1.x : ((e == e1b) ? r1.y : 0.f);
            *(__half2*)(g_xh + (long)t0 * KC + 1024 + col) =
                __floats2half2_rn(wa * acc[i][j][0], wa * acc[i][j][1]);
            *(__half2*)(g_xh + (long)t1 * KC + 1024 + col) =
                __floats2half2_rn(wb * acc[i][j][2], wb * acc[i][j][3]);
        }
    }
}

// ---------------------------------------------------------------------------
// Output GEMM (round-10 proven): C = [x|c] @ [W|Bt]^T + bias.
// BM=128, BN=64, 8 warps (4 x 2), warp tile 32x32, 2-stage, OCC=4.
// ---------------------------------------------------------------------------
__global__ void __launch_bounds__(256, 4)
gemm1(const __half* __restrict__ A, const __half* __restrict__ Bm,
      float* __restrict__ C, const float* __restrict__ bias) {
    constexpr int BM = 128, BN = 64, MI = 2, NJ = 4;
    constexpr int KT = KC / 64;                         // 18
    constexpr int STAGE_BYTES = (BM + BN) * LDH * 2;    // 27648

    extern __shared__ __align__(16) __half smem[];

    const int tid  = threadIdx.x;
    const int wid  = tid >> 5;
    const int lane = tid & 31;
    const int wm   = wid >> 1;        // 0..3
    const int wn   = wid & 1;         // 0..1
    const int g    = lane >> 2;
    const int t4   = lane & 3;
    const int m0   = blockIdx.x * BM;
    const int n0   = blockIdx.y * BN;

    const uint32_t sbase = smem_u32(smem);
    const __half* Ab = A + (long)m0 * KC;
    const __half* Bb = Bm + (long)n0 * KC;

    auto load_stage = [&](int kt, int stg) {
        const uint32_t sa = sbase + (uint32_t)stg * STAGE_BYTES;
        const uint32_t sb = sa + BM * LDH * 2;
        const __half* Asrc = Ab + (long)kt * 64;
        const __half* Bsrc = Bb + (long)kt * 64;
#pragma unroll
        for (int c = 0; c < BM * 8 / 256; c++) {
            int idx = c * 256 + tid;
            int row = idx >> 3, q = idx & 7;
            CP_ASYNC16(sa + (uint32_t)(row * LDH + q * 8) * 2,
                       Asrc + (long)row * KC + q * 8);
        }
#pragma unroll
        for (int c = 0; c < BN * 8 / 256; c++) {
            int idx = c * 256 + tid;
            int row = idx >> 3, q = idx & 7;
            CP_ASYNC16(sb + (uint32_t)(row * LDH + q * 8) * 2,
                       Bsrc + (long)row * KC + q * 8);
        }
        CP_COMMIT();
    };

    const int lrow = lane & 15;
    const int lcol = (lane >> 4) * 8;
    const uint32_t aoffh = (uint32_t)((wm * 32 + lrow) * LDH + lcol);
    const uint32_t boffh = (uint32_t)(BM * LDH + (wn * 32 + lrow) * LDH + lcol);

    float acc[MI][NJ][4];
#pragma unroll
    for (int i = 0; i < MI; i++)
#pragma unroll
        for (int j = 0; j < NJ; j++)
#pragma unroll
            for (int r = 0; r < 4; r++) acc[i][j][r] = 0.f;

    load_stage(0, 0);

    for (int kt = 0; kt < KT; kt++) {
        if (kt + 1 < KT) load_stage(kt + 1, (kt + 1) & 1);
        else CP_COMMIT();
        CP_WAIT1();
        __syncthreads();

        const uint32_t sa = sbase + (uint32_t)(kt & 1) * STAGE_BYTES;
#pragma unroll
        for (int ks = 0; ks < 4; ks++) {
            const uint32_t ksh = (uint32_t)(ks * 16) * 2;
            uint32_t a[MI][4];
#pragma unroll
            for (int i = 0; i < MI; i++)
                LDMX4(a[i][0], a[i][1], a[i][2], a[i][3],
                      sa + (aoffh + (uint32_t)(i * 16) * LDH) * 2 + ksh);
            uint32_t b[NJ][2];
#pragma unroll
            for (int jp = 0; jp < NJ / 2; jp++)
                LDMX4(b[jp * 2][0], b[jp * 2 + 1][0], b[jp * 2][1], b[jp * 2 + 1][1],
                      sa + (boffh + (uint32_t)(jp * 16) * LDH) * 2 + ksh);
#pragma unroll
            for (int i = 0; i < MI; i++)
#pragma unroll
                for (int j = 0; j < NJ; j++)
                    MMA_F16(acc[i][j], a[i], b[j]);
        }
        __syncthreads();
    }

    // Epilogue
#pragma unroll
    for (int i = 0; i < MI; i++) {
        int row0 = m0 + wm * 32 + i * 16 + g;
#pragma unroll
        for (int j = 0; j < NJ; j++) {
            int col = n0 + wn * 32 + j * 8 + 2 * t4;
            float bx = bias[col], by = bias[col + 1];
            float2 v0 = { acc[i][j][0] + bx, acc[i][j][1] + by };
            float2 v1 = { acc[i][j][2] + bx, acc[i][j][3] + by };
            *(float2*)(C + (long)row0 * DM + col)       = v0;
            *(float2*)(C + (long)(row0 + 8) * DM + col) = v1;
        }
    }
}

static constexpr int SMEM_B0 = NSTAGE * (64 + 128) * LDH * 2;  // 55296
static constexpr int SMEM_B1 = NSTAGE * (128 + 64) * LDH * 2;  // 55296

// ---------------------------------------------------------------------------
// Launch
// ---------------------------------------------------------------------------
extern "C" void kernel_launch(void* const* d_in, const int* in_sizes, int n_in,
                              void* d_out, int out_size) {
    const float* x    = (const float*)d_in[0];
    const float* Wg   = (const float*)d_in[1];
    const float* A    = (const float*)d_in[2];
    const float* B    = (const float*)d_in[3];
    const float* Wb   = (const float*)d_in[4];
    const float* bias = (const float*)d_in[5];
    float* out = (float*)d_out;

    static bool attr_done = false;
    if (!attr_done) {
        cudaFuncSetAttribute(gemm0_gate, cudaFuncAttributeMaxDynamicSharedMemorySize, SMEM_B0);
        cudaFuncSetAttribute(gemm1, cudaFuncAttributeMaxDynamicSharedMemorySize, SMEM_B1);
        attr_done = true;
    }

    __half *xh, *wh, *ah;
    cudaGetSymbolAddress((void**)&xh, g_xh);
    cudaGetSymbolAddress((void**)&wh, g_wh);
    cudaGetSymbolAddress((void**)&ah, g_ah);

    // 1) fp16 operand staging + fp32 gate logits/top-2 (one launch, overlapped)
    prep_logit_kernel<<<(int)(NPREP / 256), 256>>>(x, Wb, B, A, Wg);

    // 2) h-GEMM with fused gate epilogue -> writes c-tail of g_xh directly
    gemm0_gate<<<NTOK / 64, 256, SMEM_B0>>>(xh, ah);

    // 3) fused output GEMM: out = [x|c] @ [W|Bt]^T + bias  (8192 x 1024 x 1152)
    gemm1<<<dim3(NTOK / 128, DM / 64), 256, SMEM_B1>>>(xh, wh, out, bias);
}

// round 15
// speedup vs baseline: 1.5989x; 1.0460x over previous
#include <cuda_runtime.h>
#include <cuda_fp16.h>
#include <cstdint>

// Problem sizes
static constexpr int NTOK = 8192;
static constexpr int DM   = 1024;
static constexpr int NEXP = 8;
static constexpr int RLO  = 16;
static constexpr int KC   = 1152;   // 1024 + 128 lora-combine columns

// Scratch (device globals; no runtime allocation allowed)
__device__ __half g_xh[(long)NTOK * KC];    // [ x | c ]        (rows: token)
__device__ __half g_wh[(long)DM * KC];      // [ W_base | B^T ] (rows: out dim)
__device__ __half g_ah[128L * DM];          // ah[j][k] = A[e][k][r], j=e*16+r
__device__ float4 g_gate[NTOK];             // {w0, w1, bits(e0), bits(e1)}

// ---------------------------------------------------------------------------
// Helpers
// ---------------------------------------------------------------------------
static __device__ __forceinline__ uint32_t smem_u32(const void* p) {
    uint32_t a;
    asm("{ .reg .u64 t; cvta.to.shared.u64 t, %1; cvt.u32.u64 %0, t; }" : "=r"(a) : "l"(p));
    return a;
}

#define CP_ASYNC16(saddr, gptr) \
    asm volatile("cp.async.cg.shared.global [%0], [%1], 16;" :: "r"(saddr), "l"(gptr))
#define CP_COMMIT() asm volatile("cp.async.commit_group;" ::: "memory")
#define CP_WAIT1()  asm volatile("cp.async.wait_group 1;" ::: "memory")

// m16n8k16 fp16 MMA, fp32 accumulate
#define MMA_F16(d, a, b) \
    asm volatile("mma.sync.aligned.m16n8k16.row.col.f32.f16.f16.f32 " \
        "{%0,%1,%2,%3}, {%4,%5,%6,%7}, {%8,%9}, {%0,%1,%2,%3};" \
        : "+f"((d)[0]), "+f"((d)[1]), "+f"((d)[2]), "+f"((d)[3]) \
        : "r"((a)[0]), "r"((a)[1]), "r"((a)[2]), "r"((a)[3]), \
          "r"((b)[0]), "r"((b)[1]))

#define LDMX4(r0, r1, r2, r3, addr) \
    asm volatile("ldmatrix.sync.aligned.m8n8.x4.shared.b16 {%0,%1,%2,%3}, [%4];" \
        : "=r"(r0), "=r"(r1), "=r"(r2), "=r"(r3) : "r"(addr))

// ---------------------------------------------------------------------------
// Fused prep + gate-logit kernel (single launch).
// Segments (all boundaries 256-thread-block aligned):
//   [xlogit: 262144][W MLP4: 65536][B: 131072][A: 131072]
// xlogit: warp per token. ONE pass over x: convert to fp16 (coalesced half2
// stores into g_xh) AND accumulate the 8 fp32 gate logits; top-2 softmax.
// __launch_bounds__(256, 5) caps regs (round-13 lesson: reg bill is global).
// ---------------------------------------------------------------------------
static constexpr long NXL  = (long)NTOK * 32;       // 262144 (warp per token)
static constexpr long NW16 = (long)DM * DM / 16;    // 65536
static constexpr long NB   = 128L * DM;             // 131072
static constexpr long NA   = 128L * DM;             // 131072
static constexpr long NPREP = NXL + NW16 + NB + NA; // 589824 -> 2304 blocks

__global__ void __launch_bounds__(256, 5)
prep_logit_kernel(const float* __restrict__ x,
                  const float* __restrict__ Wb,
                  const float* __restrict__ B,
                  const float* __restrict__ A,
                  const float* __restrict__ Wg) {
    long i = (long)blockIdx.x * blockDim.x + threadIdx.x;
    if (i < NXL) {  // fused x->fp16 conversion + fp32 gate logits + top-2
        int warp = (int)(i >> 5);
        int lane = threadIdx.x & 31;
        const float4* x4 = (const float4*)(x + (long)warp * DM);
        const float4* w4 = (const float4*)Wg;
        __half2* xdst = (__half2*)(g_xh + (long)warp * KC);

        float acc[NEXP];
#pragma unroll
        for (int e = 0; e < NEXP; e++) acc[e] = 0.f;

#pragma unroll
        for (int it = 0; it < 8; it++) {
            int c4 = it * 32 + lane;            // float4 column 0..255
            float4 xa = x4[c4];
            xdst[c4 * 2]     = __floats2half2_rn(xa.x, xa.y);
            xdst[c4 * 2 + 1] = __floats2half2_rn(xa.z, xa.w);
#pragma unroll
            for (int e = 0; e < NEXP; e++) {
                float4 wv = w4[e * 256 + c4];
                acc[e] = fmaf(xa.x, wv.x, fmaf(xa.y, wv.y,
                          fmaf(xa.z, wv.z, fmaf(xa.w, wv.w, acc[e]))));
            }
        }
#pragma unroll
        for (int e = 0; e < NEXP; e++)
#pragma unroll
            for (int s = 16; s > 0; s >>= 1)
                acc[e] += __shfl_xor_sync(0xFFFFFFFFu, acc[e], s);

        if (lane == 0) {
            float v0 = -1e30f; int e0 = 0;
#pragma unroll
            for (int e = 0; e < NEXP; e++) if (acc[e] > v0) { v0 = acc[e]; e0 = e; }
            float v1 = -1e30f; int e1 = 0;
#pragma unroll
            for (int e = 0; e < NEXP; e++)
                if (e != e0 && acc[e] > v1) { v1 = acc[e]; e1 = e; }
            float b  = expf(v1 - v0);
            float w0 = 1.f / (1.f + b);
            float w1 = b * w0;
            g_gate[warp] = make_float4(w0, w1, __int_as_float(e0), __int_as_float(e1));
        }
        return;
    }
    i -= NXL;
    if (i < NW16) {
        long base4 = (i >> 8) * 1024 + (i & 255);
#pragma unroll
        for (int q = 0; q < 4; q++) {
            long i4 = base4 + q * 256;
            long n = i4 >> 8, k = (i4 & 255) * 4;
            float4 v = *(const float4*)(Wb + i4 * 4);
            __half2* dst = (__half2*)(g_wh + n * KC + k);
            dst[0] = __floats2half2_rn(v.x, v.y);
            dst[1] = __floats2half2_rn(v.z, v.w);
        }
        return;
    }
    i -= NW16;
    if (i < NB) {   // B[e][r][d] -> g_wh[d][1024 + j], j = e*16+r = i>>10
        int j = (int)(i >> 10), d = (int)(i & 1023);
        g_wh[(long)d * KC + 1024 + j] = __float2half_rn(B[i]);
        return;
    }
    i -= NB;
    if (i < NA) {   // A[e][d][r] -> g_ah[j][k] = A[e][k][r]
        int j = (int)(i >> 10), k = (int)(i & 1023);
        int e = j >> 4, r = j & 15;
        g_ah[(long)j * DM + k] = __float2half_rn(A[((long)e * DM + k) * RLO + r]);
    }
}

static constexpr int LDH = 72;                          // row pad: 64+8 halves
static constexpr int NSTAGE = 2;

// ---------------------------------------------------------------------------
// GEMM0 + gate epilogue: h[64x128] = x @ A^T (fp16 MMA, fp32 accum); epilogue
// scales h by precomputed gate weights and writes fp16 c into g_xh tail.
// BM=64, BN=128, 8 warps (2 x 4), warp tile 32x32, 2-stage, OCC=3.
// ---------------------------------------------------------------------------
__global__ void __launch_bounds__(256, 3)
gemm0_gate(const __half* __restrict__ Am, const __half* __restrict__ Bm) {
    constexpr int BM = 64, BN = 128, MI = 2, NJ = 4;
    constexpr int KT = DM / 64;                         // 16
    constexpr int STAGE_BYTES = (BM + BN) * LDH * 2;    // 27648

    extern __shared__ __align__(16) __half smem[];

    const int tid  = threadIdx.x;
    const int wid  = tid >> 5;
    const int lane = tid & 31;
    const int wm   = wid >> 2;        // 0..1
    const int wn   = wid & 3;         // 0..3
    const int g    = lane >> 2;
    const int t4   = lane & 3;
    const int m0   = blockIdx.x * BM;

    const uint32_t sbase = smem_u32(smem);
    const __half* Ab = Am + (long)m0 * KC;

    auto load_stage = [&](int kt, int stg) {
        const uint32_t sa = sbase + (uint32_t)stg * STAGE_BYTES;
        const uint32_t sb = sa + BM * LDH * 2;
        const __half* Asrc = Ab + (long)kt * 64;
        const __half* Bsrc = Bm + (long)kt * 64;
#pragma unroll
        for (int c = 0; c < BM * 8 / 256; c++) {        // 2
            int idx = c * 256 + tid;
            int row = idx >> 3, q = idx & 7;
            CP_ASYNC16(sa + (uint32_t)(row * LDH + q * 8) * 2,
                       Asrc + (long)row * KC + q * 8);
        }
#pragma unroll
        for (int c = 0; c < BN * 8 / 256; c++) {        // 4
            int idx = c * 256 + tid;
            int row = idx >> 3, q = idx & 7;
            CP_ASYNC16(sb + (uint32_t)(row * LDH + q * 8) * 2,
                       Bsrc + (long)row * DM + q * 8);
        }
        CP_COMMIT();
    };

    const int lrow = lane & 15;
    const int lcol = (lane >> 4) * 8;
    const uint32_t aoffh = (uint32_t)((wm * 32 + lrow) * LDH + lcol);
    const uint32_t boffh = (uint32_t)(BM * LDH + (wn * 32 + lrow) * LDH + lcol);

    float acc[MI][NJ][4];
#pragma unroll
    for (int i = 0; i < MI; i++)
#pragma unroll
        for (int j = 0; j < NJ; j++)
#pragma unroll
            for (int r = 0; r < 4; r++) acc[i][j][r] = 0.f;

    load_stage(0, 0);

    for (int kt = 0; kt < KT; kt++) {
        if (kt + 1 < KT) load_stage(kt + 1, (kt + 1) & 1);
        else CP_COMMIT();
        CP_WAIT1();
        __syncthreads();

        const uint32_t sa = sbase + (uint32_t)(kt & 1) * STAGE_BYTES;
#pragma unroll
        for (int ks = 0; ks < 4; ks++) {
            const uint32_t ksh = (uint32_t)(ks * 16) * 2;
            uint32_t a[MI][4];
#pragma unroll
            for (int i = 0; i < MI; i++)
                LDMX4(a[i][0], a[i][1], a[i][2], a[i][3],
                      sa + (aoffh + (uint32_t)(i * 16) * LDH) * 2 + ksh);
            uint32_t b[NJ][2];
#pragma unroll
            for (int jp = 0; jp < NJ / 2; jp++)
                LDMX4(b[jp * 2][0], b[jp * 2 + 1][0], b[jp * 2][1], b[jp * 2 + 1][1],
                      sa + (boffh + (uint32_t)(jp * 16) * LDH) * 2 + ksh);
#pragma unroll
            for (int i = 0; i < MI; i++)
#pragma unroll
                for (int j = 0; j < NJ; j++)
                    MMA_F16(acc[i][j], a[i], b[j]);
        }
        __syncthreads();
    }

    // Gate epilogue: c[token][col] = w(token, col>>4) * h ; write fp16 pairs.
#pragma unroll
    for (int i = 0; i < MI; i++) {
        int t0 = m0 + wm * 32 + i * 16 + g;
        int t1 = t0 + 8;
        float4 r0 = g_gate[t0];
        float4 r1 = g_gate[t1];
        int e0a = __float_as_int(r0.z), e1a = __float_as_int(r0.w);
        int e0b = __float_as_int(r1.z), e1b = __float_as_int(r1.w);
#pragma unroll
        for (int j = 0; j < NJ; j++) {
            int col = wn * 32 + j * 8 + 2 * t4;
            int e = col >> 4;                  // col, col+1 share the expert
            float wa = (e == e0a) ? r0.x : ((e == e1a) ? r0.y : 0.f);
            float wb = (e == e0b) ? r1.x : ((e == e1b) ? r1.y : 0.f);
            *(__half2*)(g_xh + (long)t0 * KC + 1024 + col) =
                __floats2half2_rn(wa * acc[i][j][0], wa * acc[i][j][1]);
            *(__half2*)(g_xh + (long)t1 * KC + 1024 + col) =
                __floats2half2_rn(wb * acc[i][j][2], wb * acc[i][j][3]);
        }
    }
}

// ---------------------------------------------------------------------------
// Output GEMM (round-10 proven): C = [x|c] @ [W|Bt]^T + bias.
// BM=128, BN=64, 8 warps (4 x 2), warp tile 32x32, 2-stage, OCC=4.
// ---------------------------------------------------------------------------
__global__ void __launch_bounds__(256, 4)
gemm1(const __half* __restrict__ A, const __half* __restrict__ Bm,
      float* __restrict__ C, const float* __restrict__ bias) {
    constexpr int BM = 128, BN = 64, MI = 2, NJ = 4;
    constexpr int KT = KC / 64;                         // 18
    constexpr int STAGE_BYTES = (BM + BN) * LDH * 2;    // 27648

    extern __shared__ __align__(16) __half smem[];

    const int tid  = threadIdx.x;
    const int wid  = tid >> 5;
    const int lane = tid & 31;
    const int wm   = wid >> 1;        // 0..3
    const int wn   = wid & 1;         // 0..1
    const int g    = lane >> 2;
    const int t4   = lane & 3;
    const int m0   = blockIdx.x * BM;
    const int n0   = blockIdx.y * BN;

    const uint32_t sbase = smem_u32(smem);
    const __half* Ab = A + (long)m0 * KC;
    const __half* Bb = Bm + (long)n0 * KC;

    auto load_stage = [&](int kt, int stg) {
        const uint32_t sa = sbase + (uint32_t)stg * STAGE_BYTES;
        const uint32_t sb = sa + BM * LDH * 2;
        const __half* Asrc = Ab + (long)kt * 64;
        const __half* Bsrc = Bb + (long)kt * 64;
#pragma unroll
        for (int c = 0; c < BM * 8 / 256; c++) {
            int idx = c * 256 + tid;
            int row = idx >> 3, q = idx & 7;
            CP_ASYNC16(sa + (uint32_t)(row * LDH + q * 8) * 2,
                       Asrc + (long)row * KC + q * 8);
        }
#pragma unroll
        for (int c = 0; c < BN * 8 / 256; c++) {
            int idx = c * 256 + tid;
            int row = idx >> 3, q = idx & 7;
            CP_ASYNC16(sb + (uint32_t)(row * LDH + q * 8) * 2,
                       Bsrc + (long)row * KC + q * 8);
        }
        CP_COMMIT();
    };

    const int lrow = lane & 15;
    const int lcol = (lane >> 4) * 8;
    const uint32_t aoffh = (uint32_t)((wm * 32 + lrow) * LDH + lcol);
    const uint32_t boffh = (uint32_t)(BM * LDH + (wn * 32 + lrow) * LDH + lcol);

    float acc[MI][NJ][4];
#pragma unroll
    for (int i = 0; i < MI; i++)
#pragma unroll
        for (int j = 0; j < NJ; j++)
#pragma unroll
            for (int r = 0; r < 4; r++) acc[i][j][r] = 0.f;

    load_stage(0, 0);

    for (int kt = 0; kt < KT; kt++) {
        if (kt + 1 < KT) load_stage(kt + 1, (kt + 1) & 1);
        else CP_COMMIT();
        CP_WAIT1();
        __syncthreads();

        const uint32_t sa = sbase + (uint32_t)(kt & 1) * STAGE_BYTES;
#pragma unroll
        for (int ks = 0; ks < 4; ks++) {
            const uint32_t ksh = (uint32_t)(ks * 16) * 2;
            uint32_t a[MI][4];
#pragma unroll
            for (int i = 0; i < MI; i++)
                LDMX4(a[i][0], a[i][1], a[i][2], a[i][3],
                      sa + (aoffh + (uint32_t)(i * 16) * LDH) * 2 + ksh);
            uint32_t b[NJ][2];
#pragma unroll
            for (int jp = 0; jp < NJ / 2; jp++)
                LDMX4(b[jp * 2][0], b[jp * 2 + 1][0], b[jp * 2][1], b[jp * 2 + 1][1],
                      sa + (boffh + (uint32_t)(jp * 16) * LDH) * 2 + ksh);
#pragma unroll
            for (int i = 0; i < MI; i++)
#pragma unroll
                for (int j = 0; j < NJ; j++)
                    MMA_F16(acc[i][j], a[i], b[j]);
        }
        __syncthreads();
    }

    // Epilogue
#pragma unroll
    for (int i = 0; i < MI; i++) {
        int row0 = m0 + wm * 32 + i * 16 + g;
#pragma unroll
        for (int j = 0; j < NJ; j++) {
            int col = n0 + wn * 32 + j * 8 + 2 * t4;
            float bx = bias[col], by = bias[col + 1];
            float2 v0 = { acc[i][j][0] + bx, acc[i][j][1] + by };
            float2 v1 = { acc[i][j][2] + bx, acc[i][j][3] + by };
            *(float2*)(C + (long)row0 * DM + col)       = v0;
            *(float2*)(C + (long)(row0 + 8) * DM + col) = v1;
        }
    }
}

static constexpr int SMEM_B0 = NSTAGE * (64 + 128) * LDH * 2;  // 55296
static constexpr int SMEM_B1 = NSTAGE * (128 + 64) * LDH * 2;  // 55296

// ---------------------------------------------------------------------------
// Launch
// ---------------------------------------------------------------------------
extern "C" void kernel_launch(void* const* d_in, const int* in_sizes, int n_in,
                              void* d_out, int out_size) {
    const float* x    = (const float*)d_in[0];
    const float* Wg   = (const float*)d_in[1];
    const float* A    = (const float*)d_in[2];
    const float* B    = (const float*)d_in[3];
    const float* Wb   = (const float*)d_in[4];
    const float* bias = (const float*)d_in[5];
    float* out = (float*)d_out;

    static bool attr_done = false;
    if (!attr_done) {
        cudaFuncSetAttribute(gemm0_gate, cudaFuncAttributeMaxDynamicSharedMemorySize, SMEM_B0);
        cudaFuncSetAttribute(gemm1, cudaFuncAttributeMaxDynamicSharedMemorySize, SMEM_B1);
        attr_done = true;
    }

    __half *xh, *wh, *ah;
    cudaGetSymbolAddress((void**)&xh, g_xh);
    cudaGetSymbolAddress((void**)&wh, g_wh);
    cudaGetSymbolAddress((void**)&ah, g_ah);

    // 1) single-pass x conversion + gate logits + W/B/A staging (one launch)
    prep_logit_kernel<<<(int)(NPREP / 256), 256>>>(x, Wb, B, A, Wg);

    // 2) h-GEMM with fused gate epilogue -> writes c-tail of g_xh directly
    gemm0_gate<<<NTOK / 64, 256, SMEM_B0>>>(xh, ah);

    // 3) fused output GEMM: out = [x|c] @ [W|Bt]^T + bias  (8192 x 1024 x 1152)
    gemm1<<<dim3(NTOK / 128, DM / 64), 256, SMEM_B1>>>(xh, wh, out, bias);
}

// round 16
// speedup vs baseline: 1.6674x; 1.0428x over previous
#include <cuda_runtime.h>
#include <cuda_fp16.h>
#include <cstdint>

// Problem sizes
static constexpr int NTOK = 8192;
static constexpr int DM   = 1024;
static constexpr int NEXP = 8;
static constexpr int RLO  = 16;
static constexpr int KC   = 1152;   // 1024 + 128 lora-combine columns

// Scratch (device globals; no runtime allocation allowed)
__device__ __half g_xh[(long)NTOK * KC];    // [ x | c ]        (rows: token)
__device__ __half g_wh[(long)DM * KC];      // [ W_base | B^T ] (rows: out dim)
__device__ __half g_ah[128L * DM];          // ah[j][k] = A[e][k][r], j=e*16+r
__device__ float4 g_gate[NTOK];             // {w0, w1, bits(e0), bits(e1)}

// ---------------------------------------------------------------------------
// Helpers
// ---------------------------------------------------------------------------
static __device__ __forceinline__ uint32_t smem_u32(const void* p) {
    uint32_t a;
    asm("{ .reg .u64 t; cvta.to.shared.u64 t, %1; cvt.u32.u64 %0, t; }" : "=r"(a) : "l"(p));
    return a;
}

#define CP_ASYNC16(saddr, gptr) \
    asm volatile("cp.async.cg.shared.global [%0], [%1], 16;" :: "r"(saddr), "l"(gptr))
#define CP_COMMIT() asm volatile("cp.async.commit_group;" ::: "memory")
#define CP_WAIT1()  asm volatile("cp.async.wait_group 1;" ::: "memory")

// m16n8k16 fp16 MMA, fp32 accumulate
#define MMA_F16(d, a, b) \
    asm volatile("mma.sync.aligned.m16n8k16.row.col.f32.f16.f16.f32 " \
        "{%0,%1,%2,%3}, {%4,%5,%6,%7}, {%8,%9}, {%0,%1,%2,%3};" \
        : "+f"((d)[0]), "+f"((d)[1]), "+f"((d)[2]), "+f"((d)[3]) \
        : "r"((a)[0]), "r"((a)[1]), "r"((a)[2]), "r"((a)[3]), \
          "r"((b)[0]), "r"((b)[1]))

#define LDMX4(r0, r1, r2, r3, addr) \
    asm volatile("ldmatrix.sync.aligned.m8n8.x4.shared.b16 {%0,%1,%2,%3}, [%4];" \
        : "=r"(r0), "=r"(r1), "=r"(r2), "=r"(r3) : "r"(addr))

// ---------------------------------------------------------------------------
// Fused prep + gate-logit kernel (single launch).
// Segments (all boundaries 256-thread-block aligned):
//   [xlogit T=2: 131072][W MLP4: 65536][B MLP4: 32768][A MLP4: 32768]
// xlogit: warp per 2 tokens. ONE pass over both x rows: fp16 conversion
// stores + 8 fp32 gate logits each; top-2 softmax in lane 0.
// __launch_bounds__(256, 4) = 64-reg hard cap (round-13 lesson: the worst
// segment's register bill taxes the whole kernel; cap it structurally).
// ---------------------------------------------------------------------------
static constexpr long NXL  = (long)(NTOK / 2) * 32; // 131072 (warp per 2 tokens)
static constexpr long NW16 = (long)DM * DM / 16;    // 65536
static constexpr long NB4  = 128L * DM / 4;         // 32768
static constexpr long NA4  = 128L * DM / 4;         // 32768
static constexpr long NPREP = NXL + NW16 + NB4 + NA4; // 262144 -> 1024 blocks

__global__ void __launch_bounds__(256, 4)
prep_logit_kernel(const float* __restrict__ x,
                  const float* __restrict__ Wb,
                  const float* __restrict__ B,
                  const float* __restrict__ A,
                  const float* __restrict__ Wg) {
    long i = (long)blockIdx.x * blockDim.x + threadIdx.x;
    if (i < NXL) {  // fused x->fp16 conversion + fp32 gate logits, 2 tokens
        int warp = (int)(i >> 5);
        int lane = threadIdx.x & 31;
        long t0 = (long)warp * 2;
        const float4* x4a = (const float4*)(x + t0 * DM);
        const float4* x4b = x4a + 256;
        const float4* w4  = (const float4*)Wg;
        __half2* xda = (__half2*)(g_xh + t0 * KC);
        __half2* xdb = (__half2*)(g_xh + (t0 + 1) * KC);

        float acc0[NEXP], acc1[NEXP];
#pragma unroll
        for (int e = 0; e < NEXP; e++) { acc0[e] = 0.f; acc1[e] = 0.f; }

#pragma unroll
        for (int it = 0; it < 8; it++) {
            int c4 = it * 32 + lane;            // float4 column 0..255
            float4 xa = x4a[c4];
            float4 xb = x4b[c4];
            xda[c4 * 2]     = __floats2half2_rn(xa.x, xa.y);
            xda[c4 * 2 + 1] = __floats2half2_rn(xa.z, xa.w);
            xdb[c4 * 2]     = __floats2half2_rn(xb.x, xb.y);
            xdb[c4 * 2 + 1] = __floats2half2_rn(xb.z, xb.w);
#pragma unroll
            for (int e = 0; e < NEXP; e++) {
                float4 wv = w4[e * 256 + c4];
                acc0[e] = fmaf(xa.x, wv.x, fmaf(xa.y, wv.y,
                           fmaf(xa.z, wv.z, fmaf(xa.w, wv.w, acc0[e]))));
                acc1[e] = fmaf(xb.x, wv.x, fmaf(xb.y, wv.y,
                           fmaf(xb.z, wv.z, fmaf(xb.w, wv.w, acc1[e]))));
            }
        }
#pragma unroll
        for (int e = 0; e < NEXP; e++) {
#pragma unroll
            for (int s = 16; s > 0; s >>= 1) {
                acc0[e] += __shfl_xor_sync(0xFFFFFFFFu, acc0[e], s);
                acc1[e] += __shfl_xor_sync(0xFFFFFFFFu, acc1[e], s);
            }
        }

        if (lane == 0) {
#pragma unroll
            for (int t = 0; t < 2; t++) {
                float v0 = -1e30f; int e0 = 0;
#pragma unroll
                for (int e = 0; e < NEXP; e++) {
                    float le = t ? acc1[e] : acc0[e];
                    if (le > v0) { v0 = le; e0 = e; }
                }
                float v1 = -1e30f; int e1 = 0;
#pragma unroll
                for (int e = 0; e < NEXP; e++) {
                    float le = t ? acc1[e] : acc0[e];
                    if (e != e0 && le > v1) { v1 = le; e1 = e; }
                }
                float b  = expf(v1 - v0);
                float w0 = 1.f / (1.f + b);
                float w1 = b * w0;
                g_gate[t0 + t] = make_float4(w0, w1,
                                             __int_as_float(e0), __int_as_float(e1));
            }
        }
        return;
    }
    i -= NXL;
    if (i < NW16) {
        long base4 = (i >> 8) * 1024 + (i & 255);
#pragma unroll
        for (int q = 0; q < 4; q++) {
            long i4 = base4 + q * 256;
            long n = i4 >> 8, k = (i4 & 255) * 4;
            float4 v = *(const float4*)(Wb + i4 * 4);
            __half2* dst = (__half2*)(g_wh + n * KC + k);
            dst[0] = __floats2half2_rn(v.x, v.y);
            dst[1] = __floats2half2_rn(v.z, v.w);
        }
        return;
    }
    i -= NW16;
    if (i < NB4) {  // B[j][d0..d0+3] -> g_wh[d][1024 + j], vector read, MLP-4 stores
        int j  = (int)(i >> 8);
        int d0 = (int)(i & 255) * 4;
        float4 v = *(const float4*)(B + (long)j * DM + d0);
        g_wh[(long)(d0 + 0) * KC + 1024 + j] = __float2half_rn(v.x);
        g_wh[(long)(d0 + 1) * KC + 1024 + j] = __float2half_rn(v.y);
        g_wh[(long)(d0 + 2) * KC + 1024 + j] = __float2half_rn(v.z);
        g_wh[(long)(d0 + 3) * KC + 1024 + j] = __float2half_rn(v.w);
        return;
    }
    i -= NB4;
    if (i < NA4) {  // A[e][k0..k0+3][r] -> g_ah[j][k0..k0+3], MLP-4 loads, vec store
        int j  = (int)(i >> 8);
        int k0 = (int)(i & 255) * 4;
        int e = j >> 4, r = j & 15;
        const float* Ab = A + ((long)e * DM) * RLO + r;
        float v0 = Ab[(long)(k0 + 0) * RLO];
        float v1 = Ab[(long)(k0 + 1) * RLO];
        float v2 = Ab[(long)(k0 + 2) * RLO];
        float v3 = Ab[(long)(k0 + 3) * RLO];
        __half2* dst = (__half2*)(g_ah + (long)j * DM + k0);
        dst[0] = __floats2half2_rn(v0, v1);
        dst[1] = __floats2half2_rn(v2, v3);
    }
}

static constexpr int LDH = 72;                          // row pad: 64+8 halves
static constexpr int NSTAGE = 2;

// ---------------------------------------------------------------------------
// GEMM0 + gate epilogue: h[64x128] = x @ A^T (fp16 MMA, fp32 accum); epilogue
// scales h by precomputed gate weights and writes fp16 c into g_xh tail.
// BM=64, BN=128, 8 warps (2 x 4), warp tile 32x32, 2-stage, OCC=3.
// ---------------------------------------------------------------------------
__global__ void __launch_bounds__(256, 3)
gemm0_gate(const __half* __restrict__ Am, const __half* __restrict__ Bm) {
    constexpr int BM = 64, BN = 128, MI = 2, NJ = 4;
    constexpr int KT = DM / 64;                         // 16
    constexpr int STAGE_BYTES = (BM + BN) * LDH * 2;    // 27648

    extern __shared__ __align__(16) __half smem[];

    const int tid  = threadIdx.x;
    const int wid  = tid >> 5;
    const int lane = tid & 31;
    const int wm   = wid >> 2;        // 0..1
    const int wn   = wid & 3;         // 0..3
    const int g    = lane >> 2;
    const int t4   = lane & 3;
    const int m0   = blockIdx.x * BM;

    const uint32_t sbase = smem_u32(smem);
    const __half* Ab = Am + (long)m0 * KC;

    auto load_stage = [&](int kt, int stg) {
        const uint32_t sa = sbase + (uint32_t)stg * STAGE_BYTES;
        const uint32_t sb = sa + BM * LDH * 2;
        const __half* Asrc = Ab + (long)kt * 64;
        const __half* Bsrc = Bm + (long)kt * 64;
#pragma unroll
        for (int c = 0; c < BM * 8 / 256; c++) {        // 2
            int idx = c * 256 + tid;
            int row = idx >> 3, q = idx & 7;
            CP_ASYNC16(sa + (uint32_t)(row * LDH + q * 8) * 2,
                       Asrc + (long)row * KC + q * 8);
        }
#pragma unroll
        for (int c = 0; c < BN * 8 / 256; c++) {        // 4
            int idx = c * 256 + tid;
            int row = idx >> 3, q = idx & 7;
            CP_ASYNC16(sb + (uint32_t)(row * LDH + q * 8) * 2,
                       Bsrc + (long)row * DM + q * 8);
        }
        CP_COMMIT();
    };

    const int lrow = lane & 15;
    const int lcol = (lane >> 4) * 8;
    const uint32_t aoffh = (uint32_t)((wm * 32 + lrow) * LDH + lcol);
    const uint32_t boffh = (uint32_t)(BM * LDH + (wn * 32 + lrow) * LDH + lcol);

    float acc[MI][NJ][4];
#pragma unroll
    for (int i = 0; i < MI; i++)
#pragma unroll
        for (int j = 0; j < NJ; j++)
#pragma unroll
            for (int r = 0; r < 4; r++) acc[i][j][r] = 0.f;

    load_stage(0, 0);

    for (int kt = 0; kt < KT; kt++) {
        if (kt + 1 < KT) load_stage(kt + 1, (kt + 1) & 1);
        else CP_COMMIT();
        CP_WAIT1();
        __syncthreads();

        const uint32_t sa = sbase + (uint32_t)(kt & 1) * STAGE_BYTES;
#pragma unroll
        for (int ks = 0; ks < 4; ks++) {
            const uint32_t ksh = (uint32_t)(ks * 16) * 2;
            uint32_t a[MI][4];
#pragma unroll
            for (int i = 0; i < MI; i++)
                LDMX4(a[i][0], a[i][1], a[i][2], a[i][3],
                      sa + (aoffh + (uint32_t)(i * 16) * LDH) * 2 + ksh);
            uint32_t b[NJ][2];
#pragma unroll
            for (int jp = 0; jp < NJ / 2; jp++)
                LDMX4(b[jp * 2][0], b[jp * 2 + 1][0], b[jp * 2][1], b[jp * 2 + 1][1],
                      sa + (boffh + (uint32_t)(jp * 16) * LDH) * 2 + ksh);
#pragma unroll
            for (int i = 0; i < MI; i++)
#pragma unroll
                for (int j = 0; j < NJ; j++)
                    MMA_F16(acc[i][j], a[i], b[j]);
        }
        __syncthreads();
    }

    // Gate epilogue: c[token][col] = w(token, col>>4) * h ; write fp16 pairs.
#pragma unroll
    for (int i = 0; i < MI; i++) {
        int t0 = m0 + wm * 32 + i * 16 + g;
        int t1 = t0 + 8;
        float4 r0 = g_gate[t0];
        float4 r1 = g_gate[t1];
        int e0a = __float_as_int(r0.z), e1a = __float_as_int(r0.w);
        int e0b = __float_as_int(r1.z), e1b = __float_as_int(r1.w);
#pragma unroll
        for (int j = 0; j < NJ; j++) {
            int col = wn * 32 + j * 8 + 2 * t4;
            int e = col >> 4;                  // col, col+1 share the expert
            float wa = (e == e0a) ? r0.x : ((e == e1a) ? r0.y : 0.f);
            float wb = (e == e0b) ? r1.x : ((e == e1b) ? r1.y : 0.f);
            *(__half2*)(g_xh + (long)t0 * KC + 1024 + col) =
                __floats2half2_rn(wa * acc[i][j][0], wa * acc[i][j][1]);
            *(__half2*)(g_xh + (long)t1 * KC + 1024 + col) =
                __floats2half2_rn(wb * acc[i][j][2], wb * acc[i][j][3]);
        }
    }
}

// ---------------------------------------------------------------------------
// Output GEMM (round-10 proven): C = [x|c] @ [W|Bt]^T + bias.
// BM=128, BN=64, 8 warps (4 x 2), warp tile 32x32, 2-stage, OCC=4.
// ---------------------------------------------------------------------------
__global__ void __launch_bounds__(256, 4)
gemm1(const __half* __restrict__ A, const __half* __restrict__ Bm,
      float* __restrict__ C, const float* __restrict__ bias) {
    constexpr int BM = 128, BN = 64, MI = 2, NJ = 4;
    constexpr int KT = KC / 64;                         // 18
    constexpr int STAGE_BYTES = (BM + BN) * LDH * 2;    // 27648

    extern __shared__ __align__(16) __half smem[];

    const int tid  = threadIdx.x;
    const int wid  = tid >> 5;
    const int lane = tid & 31;
    const int wm   = wid >> 1;        // 0..3
    const int wn   = wid & 1;         // 0..1
    const int g    = lane >> 2;
    const int t4   = lane & 3;
    const int m0   = blockIdx.x * BM;
    const int n0   = blockIdx.y * BN;

    const uint32_t sbase = smem_u32(smem);
    const __half* Ab = A + (long)m0 * KC;
    const __half* Bb = Bm + (long)n0 * KC;

    auto load_stage = [&](int kt, int stg) {
        const uint32_t sa = sbase + (uint32_t)stg * STAGE_BYTES;
        const uint32_t sb = sa + BM * LDH * 2;
        const __half* Asrc = Ab + (long)kt * 64;
        const __half* Bsrc = Bb + (long)kt * 64;
#pragma unroll
        for (int c = 0; c < BM * 8 / 256; c++) {
            int idx = c * 256 + tid;
            int row = idx >> 3, q = idx & 7;
            CP_ASYNC16(sa + (uint32_t)(row * LDH + q * 8) * 2,
                       Asrc + (long)row * KC + q * 8);
        }
#pragma unroll
        for (int c = 0; c < BN * 8 / 256; c++) {
            int idx = c * 256 + tid;
            int row = idx >> 3, q = idx & 7;
            CP_ASYNC16(sb + (uint32_t)(row * LDH + q * 8) * 2,
                       Bsrc + (long)row * KC + q * 8);
        }
        CP_COMMIT();
    };

    const int lrow = lane & 15;
    const int lcol = (lane >> 4) * 8;
    const uint32_t aoffh = (uint32_t)((wm * 32 + lrow) * LDH + lcol);
    const uint32_t boffh = (uint32_t)(BM * LDH + (wn * 32 + lrow) * LDH + lcol);

    float acc[MI][NJ][4];
#pragma unroll
    for (int i = 0; i < MI; i++)
#pragma unroll
        for (int j = 0; j < NJ; j++)
#pragma unroll
            for (int r = 0; r < 4; r++) acc[i][j][r] = 0.f;

    load_stage(0, 0);

    for (int kt = 0; kt < KT; kt++) {
        if (kt + 1 < KT) load_stage(kt + 1, (kt + 1) & 1);
        else CP_COMMIT();
        CP_WAIT1();
        __syncthreads();

        const uint32_t sa = sbase + (uint32_t)(kt & 1) * STAGE_BYTES;
#pragma unroll
        for (int ks = 0; ks < 4; ks++) {
            const uint32_t ksh = (uint32_t)(ks * 16) * 2;
            uint32_t a[MI][4];
#pragma unroll
            for (int i = 0; i < MI; i++)
                LDMX4(a[i][0], a[i][1], a[i][2], a[i][3],
                      sa + (aoffh + (uint32_t)(i * 16) * LDH) * 2 + ksh);
            uint32_t b[NJ][2];
#pragma unroll
            for (int jp = 0; jp < NJ / 2; jp++)
                LDMX4(b[jp * 2][0], b[jp * 2 + 1][0], b[jp * 2][1], b[jp * 2 + 1][1],
                      sa + (boffh + (uint32_t)(jp * 16) * LDH) * 2 + ksh);
#pragma unroll
            for (int i = 0; i < MI; i++)
#pragma unroll
                for (int j = 0; j < NJ; j++)
                    MMA_F16(acc[i][j], a[i], b[j]);
        }
        __syncthreads();
    }

    // Epilogue
#pragma unroll
    for (int i = 0; i < MI; i++) {
        int row0 = m0 + wm * 32 + i * 16 + g;
#pragma unroll
        for (int j = 0; j < NJ; j++) {
            int col = n0 + wn * 32 + j * 8 + 2 * t4;
            float bx = bias[col], by = bias[col + 1];
            float2 v0 = { acc[i][j][0] + bx, acc[i][j][1] + by };
            float2 v1 = { acc[i][j][2] + bx, acc[i][j][3] + by };
            *(float2*)(C + (long)row0 * DM + col)       = v0;
            *(float2*)(C + (long)(row0 + 8) * DM + col) = v1;
        }
    }
}

static constexpr int SMEM_B0 = NSTAGE * (64 + 128) * LDH * 2;  // 55296
static constexpr int SMEM_B1 = NSTAGE * (128 + 64) * LDH * 2;  // 55296

// ---------------------------------------------------------------------------
// Launch
// ---------------------------------------------------------------------------
extern "C" void kernel_launch(void* const* d_in, const int* in_sizes, int n_in,
                              void* d_out, int out_size) {
    const float* x    = (const float*)d_in[0];
    const float* Wg   = (const float*)d_in[1];
    const float* A    = (const float*)d_in[2];
    const float* B    = (const float*)d_in[3];
    const float* Wb   = (const float*)d_in[4];
    const float* bias = (const float*)d_in[5];
    float* out = (float*)d_out;

    static bool attr_done = false;
    if (!attr_done) {
        cudaFuncSetAttribute(gemm0_gate, cudaFuncAttributeMaxDynamicSharedMemorySize, SMEM_B0);
        cudaFuncSetAttribute(gemm1, cudaFuncAttributeMaxDynamicSharedMemorySize, SMEM_B1);
        attr_done = true;
    }

    __half *xh, *wh, *ah;
    cudaGetSymbolAddress((void**)&xh, g_xh);
    cudaGetSymbolAddress((void**)&wh, g_wh);
    cudaGetSymbolAddress((void**)&ah, g_ah);

    // 1) single-pass x conversion + gate logits + W/B/A staging (one launch)
    prep_logit_kernel<<<(int)(NPREP / 256), 256>>>(x, Wb, B, A, Wg);

    // 2) h-GEMM with fused gate epilogue -> writes c-tail of g_xh directly
    gemm0_gate<<<NTOK / 64, 256, SMEM_B0>>>(xh, ah);

    // 3) fused output GEMM: out = [x|c] @ [W|Bt]^T + bias  (8192 x 1024 x 1152)
    gemm1<<<dim3(NTOK / 128, DM / 64), 256, SMEM_B1>>>(xh, wh, out, bias);
}